// round 6
// baseline (speedup 1.0000x reference)
#include <cuda_runtime.h>
#include <cuda_fp16.h>
#include <cstdint>

// Problem constants
#define B_    16
#define CIN   256
#define COUT  128
#define HW    64
#define OHW   128
#define KDIM  1024        // k' = q*256 + ci   (q = ty*2+tx tap index)
#define KS    64          // k' per pipeline stage
#define NK    16          // KDIM / KS
#define XP    66          // padded spatial extent
#define NSTG  3
#define NTILE 256         // CTA N tile (spatial positions)
#define STG_BYTES 49152   // A 16KB + B 32KB per stage

// Scratch
//  g_wsyn[b][p][co][k']   half, 16 MB
//  g_xc[b][row][col][ci]  half NHWC, zero border, 35.7 MB
__device__ __align__(16) __half g_wsyn[(size_t)B_ * 4 * COUT * KDIM];
__device__ __align__(16) __half g_xc[(size_t)B_ * XP * XP * CIN];

#define SWZ(o) ((o) ^ (((o) >> 3) & 0x70))

static __device__ __forceinline__ void mma16816(float c[4], unsigned a0, unsigned a1,
                                                unsigned a2, unsigned a3,
                                                unsigned b0, unsigned b1) {
    asm volatile(
        "mma.sync.aligned.m16n8k16.row.col.f32.f16.f16.f32 "
        "{%0,%1,%2,%3}, {%4,%5,%6,%7}, {%8,%9}, {%0,%1,%2,%3};\n"
        : "+f"(c[0]), "+f"(c[1]), "+f"(c[2]), "+f"(c[3])
        : "r"(a0), "r"(a1), "r"(a2), "r"(a3), "r"(b0), "r"(b1));
}
static __device__ __forceinline__ void ldsm4(unsigned r[4], unsigned addr) {
    asm volatile("ldmatrix.sync.aligned.m8n8.x4.shared.b16 {%0,%1,%2,%3}, [%4];"
                 : "=r"(r[0]), "=r"(r[1]), "=r"(r[2]), "=r"(r[3]) : "r"(addr));
}
static __device__ __forceinline__ void cpasync16(unsigned dst, const void* src) {
    asm volatile("cp.async.cg.shared.global [%0], [%1], 16;" :: "r"(dst), "l"(src));
}

// ---------------------------------------------------------------------------
// Fused front-end: prep (blocks 0..1055) + weight synth (blocks 1056..1311).
// ---------------------------------------------------------------------------
#define PREP_BLOCKS (XP * B_)   // 1056

__global__ void __launch_bounds__(256) front_kernel(
    const float* __restrict__ x,
    const float* __restrict__ feature, const float* __restrict__ weight,
    const float* __restrict__ t0, const float* __restrict__ t1,
    const float* __restrict__ t2, const float* __restrict__ t3,
    const float* __restrict__ m0, const float* __restrict__ m1,
    const float* __restrict__ m2, const float* __restrict__ m3) {
    __shared__ __align__(16) __half sh[64 * 264];
    const int t = threadIdx.x;

    if (blockIdx.x < PREP_BLOCKS) {
        const int row = blockIdx.x % XP;
        const int b   = blockIdx.x / XP;
        __half* dst = g_xc + ((size_t)b * XP + row) * XP * CIN;

        if (row == 0 || row == XP - 1) {
            for (int i = t; i < XP * CIN / 8; i += 256)
                ((uint4*)dst)[i] = make_uint4(0, 0, 0, 0);
            return;
        }
        const int y = row - 1;
        const float* xr = x + (((size_t)b * CIN + t) * HW + y) * HW;
#pragma unroll
        for (int x4 = 0; x4 < 16; x4++) {
            float4 v = ((const float4*)xr)[x4];
            int xx = x4 * 4;
            sh[(xx + 0) * 264 + t] = __float2half(v.x);
            sh[(xx + 1) * 264 + t] = __float2half(v.y);
            sh[(xx + 2) * 264 + t] = __float2half(v.z);
            sh[(xx + 3) * 264 + t] = __float2half(v.w);
        }
        __syncthreads();
        {
            int col = 1 + (t >> 2);
            int ch  = (t & 3) * 64;
            uint4* d4 = (uint4*)(dst + (size_t)col * CIN + ch);
            const uint4* s4 = (const uint4*)(sh + (col - 1) * 264 + ch);
#pragma unroll
            for (int i = 0; i < 8; i++) d4[i] = s4[i];
        }
        if (t < 64) {
            int c = (t < 32) ? 0 : (XP - 1);
            ((uint4*)(dst + (size_t)c * CIN))[t & 31] = make_uint4(0, 0, 0, 0);
        }
    } else {
        __shared__ float sf[B_ * 4];
        if (t < B_ * 4) sf[t] = feature[t];
        __syncthreads();

        int idx = (blockIdx.x - PREP_BLOCKS) * 256 + t;
        int kx  = idx & 3;
        int ky  = (idx >> 2) & 3;
        int co  = (idx >> 4) & (COUT - 1);
        int ci0 = (idx >> 11) * 8;

        float w[8], a0[8], a1[8], a2[8], a3[8];
#pragma unroll
        for (int i = 0; i < 8; i++) {
            int ci  = ci0 + i;
            int off = (ci * COUT + co) * 16 + ky * 4 + kx;
            int mi  = ci * COUT + co;
            w[i]  = weight[off];
            a0[i] = t0[off] * m0[mi];
            a1[i] = t1[off] * m1[mi];
            a2[i] = t2[off] * m2[mi];
            a3[i] = t3[off] * m3[mi];
        }
        int py = 1 - (ky & 1);
        int px = 1 - (kx & 1);
        int dy = (py + 1 - ky) / 2;
        int dx = (px + 1 - kx) / 2;
        int ty = dy + 1 - py;
        int tx = dx + 1 - px;
        int p  = py * 2 + px;
        int q  = ty * 2 + tx;

        size_t base     = ((size_t)p * COUT + co) * KDIM + q * 256 + ci0;
        size_t stride_b = (size_t)4 * COUT * KDIM;
#pragma unroll
        for (int b = 0; b < B_; b++) {
            const float* f = sf + b * 4;
            __align__(16) __half h[8];
#pragma unroll
            for (int i = 0; i < 8; i++)
                h[i] = __float2half(w[i] + a0[i] * f[0] + a1[i] * f[1] +
                                    a2[i] * f[2] + a3[i] * f[3]);
            *(uint4*)(g_wsyn + b * stride_b + base) = *(uint4*)h;
        }
    }
}

// ---------------------------------------------------------------------------
// GEMM: mma.sync m16n8k16, 3-stage cp.async pipeline.
// CTA per (b, p, 256-spatial tile): M=128(co) x N=256(n) x K=1024.
// 8 warps 2(m) x 4(n), warp tile 64x64 (raises smem arithmetic intensity).
// ---------------------------------------------------------------------------
__global__ void __launch_bounds__(256, 1)
deconv_mma_kernel(const float* __restrict__ bias,
                  const float* __restrict__ prelu_a,
                  float* __restrict__ out) {
    extern __shared__ __align__(1024) char smem[];
    const unsigned sb = (unsigned)__cvta_generic_to_shared(smem);
    const int tid  = threadIdx.x;
    const int lane = tid & 31;
    const int warp = tid >> 5;
    const int warp_m = warp >> 2;
    const int warp_n = warp & 3;
    const int b  = blockIdx.z;
    const int p  = blockIdx.y;
    const int py = p >> 1, px = p & 1;
    const int n0 = blockIdx.x * NTILE;
    const int y0 = n0 >> 6;

    const __half* wb = g_wsyn + (size_t)(b * 4 + p) * COUT * KDIM;
    const __half* xb = g_xc + (size_t)b * XP * XP * CIN;

    float acc[4][8][4];
#pragma unroll
    for (int i = 0; i < 4; i++)
#pragma unroll
        for (int j = 0; j < 8; j++)
#pragma unroll
            for (int r = 0; r < 4; r++) acc[i][j][r] = 0.f;

    auto fill = [&](int ks, int buf) {
        const unsigned ab = sb + buf * STG_BYTES;
        const unsigned bb = ab + 16384;
        const int k0 = ks * KS;
        // A: 128 co rows x 128B
#pragma unroll
        for (int i = 0; i < 4; i++) {
            int seg = tid + i * 256;
            int co = seg >> 3, s8 = seg & 7;
            cpasync16(ab + SWZ(co * 128 + s8 * 16),
                      wb + (size_t)co * KDIM + k0 + s8 * 8);
        }
        // B: 256 n rows x 128B
        const int q  = ks >> 2;
        const int ty = q >> 1, tx = q & 1;
        const int ci0 = (ks & 3) * 64;
#pragma unroll
        for (int i = 0; i < 8; i++) {
            int seg = tid + i * 256;
            int n = seg >> 3, s8 = seg & 7;
            int yy  = y0 + (n >> 6) + ty + py;
            int xx2 = (n & 63) + tx + px;
            cpasync16(bb + SWZ(n * 128 + s8 * 16),
                      xb + ((size_t)yy * XP + xx2) * CIN + ci0 + s8 * 8);
        }
        asm volatile("cp.async.commit_group;" ::: "memory");
    };

    auto compute = [&](int buf) {
        const unsigned ab = sb + buf * STG_BYTES;
        const unsigned bb = ab + 16384;
#pragma unroll
        for (int kk = 0; kk < 4; kk++) {
            const int kb = kk * 32 + (lane >> 4) * 16;
            unsigned afr[4][4];
#pragma unroll
            for (int mi = 0; mi < 4; mi++) {
                int row = warp_m * 64 + mi * 16 + (lane & 15);
                ldsm4(afr[mi], ab + SWZ(row * 128 + kb));
            }
            unsigned bfr[4][4];
#pragma unroll
            for (int g = 0; g < 4; g++) {
                int rown = warp_n * 64 + g * 16 + (lane & 15);
                ldsm4(bfr[g], bb + SWZ(rown * 128 + kb));
            }
#pragma unroll
            for (int mi = 0; mi < 4; mi++)
#pragma unroll
                for (int nj = 0; nj < 8; nj++)
                    mma16816(acc[mi][nj], afr[mi][0], afr[mi][1], afr[mi][2],
                             afr[mi][3], bfr[nj >> 1][nj & 1],
                             bfr[nj >> 1][(nj & 1) + 2]);
        }
    };

    fill(0, 0);
    fill(1, 1);
    for (int ks = 0; ks < NK; ks++) {
        if (ks == NK - 1)
            asm volatile("cp.async.wait_group 0;" ::: "memory");
        else
            asm volatile("cp.async.wait_group 1;" ::: "memory");
        __syncthreads();
        if (ks + 2 < NK) fill(ks + 2, (ks + 2) % NSTG);
        compute(ks % NSTG);
    }

    // --- epilogue: bias + PReLU + stride-2 phase scatter ---
    const float alpha = prelu_a[0];
#pragma unroll
    for (int mi = 0; mi < 4; mi++) {
        const int rbase = warp_m * 64 + mi * 16 + (lane >> 2);
#pragma unroll
        for (int hm = 0; hm < 2; hm++) {
            const int co = rbase + hm * 8;
            const float bv = bias[co];
            float* obase = out + ((size_t)b * COUT + co) * OHW * OHW;
#pragma unroll
            for (int nj = 0; nj < 8; nj++) {
#pragma unroll
                for (int u = 0; u < 2; u++) {
                    int n  = n0 + warp_n * 64 + nj * 8 + (lane & 3) * 2 + u;
                    int y  = n >> 6;
                    int xx = n & 63;
                    int oy = 2 * y + py;
                    int ox = 2 * xx + px;
                    float v = acc[mi][nj][hm * 2 + u] + bv;
                    v = (v >= 0.f) ? v : alpha * v;
                    obase[oy * OHW + ox] = v;
                }
            }
        }
    }
}

// ---------------------------------------------------------------------------
// Launch
// ---------------------------------------------------------------------------
extern "C" void kernel_launch(void* const* d_in, const int* in_sizes, int n_in,
                              void* d_out, int out_size) {
    const float* x       = (const float*)d_in[0];
    const float* feature = (const float*)d_in[1];
    const float* weight  = (const float*)d_in[2];
    const float* t0      = (const float*)d_in[3];
    const float* t1      = (const float*)d_in[4];
    const float* t2      = (const float*)d_in[5];
    const float* t3      = (const float*)d_in[6];
    const float* m0      = (const float*)d_in[7];
    const float* m1      = (const float*)d_in[8];
    const float* m2      = (const float*)d_in[9];
    const float* m3      = (const float*)d_in[10];
    const float* bias    = (const float*)d_in[11];
    const float* prelu_a = (const float*)d_in[12];
    float* out = (float*)d_out;

    {
        int blocks = PREP_BLOCKS + (CIN / 8) * COUT * 16 / 256;  // 1056 + 256
        front_kernel<<<blocks, 256>>>(x, feature, weight, t0, t1, t2, t3,
                                      m0, m1, m2, m3);
    }
    {
        cudaFuncSetAttribute(deconv_mma_kernel,
                             cudaFuncAttributeMaxDynamicSharedMemorySize,
                             NSTG * STG_BYTES);
        dim3 grid(HW * HW / NTILE, 4, B_);   // 16 x 4 x 16
        deconv_mma_kernel<<<grid, 256, NSTG * STG_BYTES>>>(bias, prelu_a, out);
    }
}

// round 8
// speedup vs baseline: 1.0147x; 1.0147x over previous
#include <cuda_runtime.h>
#include <cuda_fp16.h>
#include <cstdint>

// Problem constants
#define B_    16
#define CIN   256
#define COUT  128
#define HW    64
#define OHW   128
#define KDIM  1024        // k' = q*256 + ci   (q = ty*2+tx tap index)
#define KS    64          // k' per pipeline stage
#define NK    16          // KDIM / KS
#define XP    66          // padded spatial extent
#define NSTG  4
#define NTILE 256         // CTA N tile (spatial positions)
#define STG_BYTES 49152   // A 16KB + B 32KB per stage

// Scratch
__device__ __align__(16) __half g_wsyn[(size_t)B_ * 4 * COUT * KDIM];
__device__ __align__(16) __half g_xc[(size_t)B_ * XP * XP * CIN];

#define SWZ(o) ((o) ^ (((o) >> 3) & 0x70))

static __device__ __forceinline__ void mma16816(float c[4], unsigned a0, unsigned a1,
                                                unsigned a2, unsigned a3,
                                                unsigned b0, unsigned b1) {
    asm volatile(
        "mma.sync.aligned.m16n8k16.row.col.f32.f16.f16.f32 "
        "{%0,%1,%2,%3}, {%4,%5,%6,%7}, {%8,%9}, {%0,%1,%2,%3};\n"
        : "+f"(c[0]), "+f"(c[1]), "+f"(c[2]), "+f"(c[3])
        : "r"(a0), "r"(a1), "r"(a2), "r"(a3), "r"(b0), "r"(b1));
}
static __device__ __forceinline__ void ldsm4(unsigned r[4], unsigned addr) {
    asm volatile("ldmatrix.sync.aligned.m8n8.x4.shared.b16 {%0,%1,%2,%3}, [%4];"
                 : "=r"(r[0]), "=r"(r[1]), "=r"(r[2]), "=r"(r[3]) : "r"(addr));
}
static __device__ __forceinline__ void cpasync16(unsigned dst, const void* src) {
    asm volatile("cp.async.cg.shared.global [%0], [%1], 16;" :: "r"(dst), "l"(src));
}

// ---------------------------------------------------------------------------
// Fused front-end: prep (blocks 0..1055) + weight synth (blocks 1056..1311).
// ---------------------------------------------------------------------------
#define PREP_BLOCKS (XP * B_)   // 1056

__global__ void __launch_bounds__(256) front_kernel(
    const float* __restrict__ x,
    const float* __restrict__ feature, const float* __restrict__ weight,
    const float* __restrict__ t0, const float* __restrict__ t1,
    const float* __restrict__ t2, const float* __restrict__ t3,
    const float* __restrict__ m0, const float* __restrict__ m1,
    const float* __restrict__ m2, const float* __restrict__ m3) {
    __shared__ __align__(16) __half sh[64 * 264];
    const int t = threadIdx.x;

    if (blockIdx.x < PREP_BLOCKS) {
        const int row = blockIdx.x % XP;
        const int b   = blockIdx.x / XP;
        __half* dst = g_xc + ((size_t)b * XP + row) * XP * CIN;

        if (row == 0 || row == XP - 1) {
            for (int i = t; i < XP * CIN / 8; i += 256)
                ((uint4*)dst)[i] = make_uint4(0, 0, 0, 0);
            return;
        }
        const int y = row - 1;
        const float* xr = x + (((size_t)b * CIN + t) * HW + y) * HW;
#pragma unroll
        for (int x4 = 0; x4 < 16; x4++) {
            float4 v = ((const float4*)xr)[x4];
            int xx = x4 * 4;
            sh[(xx + 0) * 264 + t] = __float2half(v.x);
            sh[(xx + 1) * 264 + t] = __float2half(v.y);
            sh[(xx + 2) * 264 + t] = __float2half(v.z);
            sh[(xx + 3) * 264 + t] = __float2half(v.w);
        }
        __syncthreads();
        {
            int col = 1 + (t >> 2);
            int ch  = (t & 3) * 64;
            uint4* d4 = (uint4*)(dst + (size_t)col * CIN + ch);
            const uint4* s4 = (const uint4*)(sh + (col - 1) * 264 + ch);
#pragma unroll
            for (int i = 0; i < 8; i++) d4[i] = s4[i];
        }
        if (t < 64) {
            int c = (t < 32) ? 0 : (XP - 1);
            ((uint4*)(dst + (size_t)c * CIN))[t & 31] = make_uint4(0, 0, 0, 0);
        }
    } else {
        __shared__ float sf[B_ * 4];
        if (t < B_ * 4) sf[t] = feature[t];
        __syncthreads();

        int idx = (blockIdx.x - PREP_BLOCKS) * 256 + t;
        int kx  = idx & 3;
        int ky  = (idx >> 2) & 3;
        int co  = (idx >> 4) & (COUT - 1);
        int ci0 = (idx >> 11) * 8;

        float w[8], a0[8], a1[8], a2[8], a3[8];
#pragma unroll
        for (int i = 0; i < 8; i++) {
            int ci  = ci0 + i;
            int off = (ci * COUT + co) * 16 + ky * 4 + kx;
            int mi  = ci * COUT + co;
            w[i]  = weight[off];
            a0[i] = t0[off] * m0[mi];
            a1[i] = t1[off] * m1[mi];
            a2[i] = t2[off] * m2[mi];
            a3[i] = t3[off] * m3[mi];
        }
        int py = 1 - (ky & 1);
        int px = 1 - (kx & 1);
        int dy = (py + 1 - ky) / 2;
        int dx = (px + 1 - kx) / 2;
        int ty = dy + 1 - py;
        int tx = dx + 1 - px;
        int p  = py * 2 + px;
        int q  = ty * 2 + tx;

        size_t base     = ((size_t)p * COUT + co) * KDIM + q * 256 + ci0;
        size_t stride_b = (size_t)4 * COUT * KDIM;
#pragma unroll
        for (int b = 0; b < B_; b++) {
            const float* f = sf + b * 4;
            __align__(16) __half h[8];
#pragma unroll
            for (int i = 0; i < 8; i++)
                h[i] = __float2half(w[i] + a0[i] * f[0] + a1[i] * f[1] +
                                    a2[i] * f[2] + a3[i] * f[3]);
            *(uint4*)(g_wsyn + b * stride_b + base) = *(uint4*)h;
        }
    }
}

// ---------------------------------------------------------------------------
// GEMM: mma.sync m16n8k16, 4-stage depth-3 cp.async pipeline,
// warp tile 64x64, register double-buffered fragments across kk.
// Fragment addressing: SWZ(row*128 + kb) = row*128 + (kb ^ ((row&7)<<4))
// (valid because kb < 128 occupies bits [4:6] and row*128 has low bits 0).
// ---------------------------------------------------------------------------
__global__ void __launch_bounds__(256, 1)
deconv_mma_kernel(const float* __restrict__ bias,
                  const float* __restrict__ prelu_a,
                  float* __restrict__ out) {
    extern __shared__ __align__(1024) char smem[];
    const unsigned sb = (unsigned)__cvta_generic_to_shared(smem);
    const int tid  = threadIdx.x;
    const int lane = tid & 31;
    const int warp = tid >> 5;
    const int warp_m = warp >> 2;
    const int warp_n = warp & 3;
    const int b  = blockIdx.z;
    const int p  = blockIdx.y;
    const int py = p >> 1, px = p & 1;
    const int n0 = blockIdx.x * NTILE;
    const int y0 = n0 >> 6;

    const __half* wb = g_wsyn + (size_t)(b * 4 + p) * COUT * KDIM;
    const __half* xb = g_xc + (size_t)b * XP * XP * CIN;

    // Fragment row bases (no swizzle) + per-fragment swizzle masks.
    unsigned araw[4], amask[4], braw[4], bmask[4];
#pragma unroll
    for (int mi = 0; mi < 4; mi++) {
        int row = warp_m * 64 + mi * 16 + (lane & 15);
        araw[mi]  = row * 128;
        amask[mi] = (row & 7) << 4;
    }
#pragma unroll
    for (int g = 0; g < 4; g++) {
        int rown = warp_n * 64 + g * 16 + (lane & 15);
        braw[g]  = rown * 128;
        bmask[g] = (rown & 7) << 4;
    }
    const int kbl = (lane >> 4) * 16;

    float acc[4][8][4];
#pragma unroll
    for (int i = 0; i < 4; i++)
#pragma unroll
        for (int j = 0; j < 8; j++)
#pragma unroll
            for (int r = 0; r < 4; r++) acc[i][j][r] = 0.f;

    auto fill = [&](int ks, int buf) {
        const unsigned ab = sb + buf * STG_BYTES;
        const unsigned bb = ab + 16384;
        const int k0 = ks * KS;
#pragma unroll
        for (int i = 0; i < 4; i++) {
            int seg = tid + i * 256;
            int co = seg >> 3, s8 = seg & 7;
            cpasync16(ab + SWZ(co * 128 + s8 * 16),
                      wb + (size_t)co * KDIM + k0 + s8 * 8);
        }
        const int q  = ks >> 2;
        const int ty = q >> 1, tx = q & 1;
        const int ci0 = (ks & 3) * 64;
#pragma unroll
        for (int i = 0; i < 8; i++) {
            int seg = tid + i * 256;
            int n = seg >> 3, s8 = seg & 7;
            int yy  = y0 + (n >> 6) + ty + py;
            int xx2 = (n & 63) + tx + px;
            cpasync16(bb + SWZ(n * 128 + s8 * 16),
                      xb + ((size_t)yy * XP + xx2) * CIN + ci0 + s8 * 8);
        }
        asm volatile("cp.async.commit_group;" ::: "memory");
    };

    auto compute = [&](int buf) {
        const unsigned ab = sb + buf * STG_BYTES;
        const unsigned bb = ab + 16384;
        unsigned afr[2][4][4], bfr[2][4][4];
        // preload kk=0 fragments (kkb = kbl)
#pragma unroll
        for (int mi = 0; mi < 4; mi++)
            ldsm4(afr[0][mi], ab + araw[mi] + ((unsigned)kbl ^ amask[mi]));
#pragma unroll
        for (int g = 0; g < 4; g++)
            ldsm4(bfr[0][g], bb + braw[g] + ((unsigned)kbl ^ bmask[g]));
#pragma unroll
        for (int kk = 0; kk < 4; kk++) {
            const int cur = kk & 1, nxt = cur ^ 1;
            if (kk < 3) {
                const unsigned kkb = (unsigned)(kbl + (kk + 1) * 32);
#pragma unroll
                for (int mi = 0; mi < 4; mi++)
                    ldsm4(afr[nxt][mi], ab + araw[mi] + (kkb ^ amask[mi]));
#pragma unroll
                for (int g = 0; g < 4; g++)
                    ldsm4(bfr[nxt][g], bb + braw[g] + (kkb ^ bmask[g]));
            }
#pragma unroll
            for (int mi = 0; mi < 4; mi++)
#pragma unroll
                for (int nj = 0; nj < 8; nj++)
                    mma16816(acc[mi][nj], afr[cur][mi][0], afr[cur][mi][1],
                             afr[cur][mi][2], afr[cur][mi][3],
                             bfr[cur][nj >> 1][nj & 1],
                             bfr[cur][nj >> 1][(nj & 1) + 2]);
        }
    };

    fill(0, 0);
    fill(1, 1);
    fill(2, 2);
    for (int ks = 0; ks < NK; ks++) {
        if (ks == NK - 1)
            asm volatile("cp.async.wait_group 0;" ::: "memory");
        else
            asm volatile("cp.async.wait_group 2;" ::: "memory");
        __syncthreads();
        if (ks + 3 < NK) fill(ks + 3, (ks + 3) & 3);
        compute(ks & 3);
    }

    // --- epilogue: bias + PReLU + stride-2 phase scatter ---
    const float alpha = prelu_a[0];
#pragma unroll
    for (int mi = 0; mi < 4; mi++) {
        const int rbase = warp_m * 64 + mi * 16 + (lane >> 2);
#pragma unroll
        for (int hm = 0; hm < 2; hm++) {
            const int co = rbase + hm * 8;
            const float bv = bias[co];
            float* obase = out + ((size_t)b * COUT + co) * OHW * OHW;
#pragma unroll
            for (int nj = 0; nj < 8; nj++) {
#pragma unroll
                for (int u = 0; u < 2; u++) {
                    int n  = n0 + warp_n * 64 + nj * 8 + (lane & 3) * 2 + u;
                    int y  = n >> 6;
                    int xx = n & 63;
                    int oy = 2 * y + py;
                    int ox = 2 * xx + px;
                    float v = acc[mi][nj][hm * 2 + u] + bv;
                    v = (v >= 0.f) ? v : alpha * v;
                    obase[oy * OHW + ox] = v;
                }
            }
        }
    }
}

// ---------------------------------------------------------------------------
// Launch
// ---------------------------------------------------------------------------
extern "C" void kernel_launch(void* const* d_in, const int* in_sizes, int n_in,
                              void* d_out, int out_size) {
    const float* x       = (const float*)d_in[0];
    const float* feature = (const float*)d_in[1];
    const float* weight  = (const float*)d_in[2];
    const float* t0      = (const float*)d_in[3];
    const float* t1      = (const float*)d_in[4];
    const float* t2      = (const float*)d_in[5];
    const float* t3      = (const float*)d_in[6];
    const float* m0      = (const float*)d_in[7];
    const float* m1      = (const float*)d_in[8];
    const float* m2      = (const float*)d_in[9];
    const float* m3      = (const float*)d_in[10];
    const float* bias    = (const float*)d_in[11];
    const float* prelu_a = (const float*)d_in[12];
    float* out = (float*)d_out;

    {
        int blocks = PREP_BLOCKS + (CIN / 8) * COUT * 16 / 256;  // 1056 + 256
        front_kernel<<<blocks, 256>>>(x, feature, weight, t0, t1, t2, t3,
                                      m0, m1, m2, m3);
    }
    {
        cudaFuncSetAttribute(deconv_mma_kernel,
                             cudaFuncAttributeMaxDynamicSharedMemorySize,
                             NSTG * STG_BYTES);
        dim3 grid(HW * HW / NTILE, 4, B_);   // 16 x 4 x 16
        deconv_mma_kernel<<<grid, 256, NSTG * STG_BYTES>>>(bias, prelu_a, out);
    }
}

// round 10
// speedup vs baseline: 1.0916x; 1.0758x over previous
#include <cuda_runtime.h>
#include <cuda_fp16.h>
#include <cstdint>

// Problem constants
#define B_    16
#define CIN   256
#define COUT  128
#define HW    64
#define OHW   128
#define KDIM  1024        // k' = q*256 + ci   (q = ty*2+tx tap index)
#define KS    64          // k' per pipeline stage
#define NK    16          // KDIM / KS
#define XP    66          // padded spatial extent
#define NSLOT 4
#define NTILE 256         // CTA N tile (spatial positions)
#define STG_BYTES 49152   // A 16KB + B 32KB per slot
#define NTHREADS 320      // 8 consumer warps + 2 producer warps

// Scratch
__device__ __align__(16) __half g_wsyn[(size_t)B_ * 4 * COUT * KDIM];
__device__ __align__(16) __half g_xc[(size_t)B_ * XP * XP * CIN];

#define SWZ(o) ((o) ^ (((o) >> 3) & 0x70))

static __device__ __forceinline__ void mma16816(float c[4], unsigned a0, unsigned a1,
                                                unsigned a2, unsigned a3,
                                                unsigned b0, unsigned b1) {
    asm volatile(
        "mma.sync.aligned.m16n8k16.row.col.f32.f16.f16.f32 "
        "{%0,%1,%2,%3}, {%4,%5,%6,%7}, {%8,%9}, {%0,%1,%2,%3};\n"
        : "+f"(c[0]), "+f"(c[1]), "+f"(c[2]), "+f"(c[3])
        : "r"(a0), "r"(a1), "r"(a2), "r"(a3), "r"(b0), "r"(b1));
}
static __device__ __forceinline__ void ldsm4(unsigned r[4], unsigned addr) {
    asm volatile("ldmatrix.sync.aligned.m8n8.x4.shared.b16 {%0,%1,%2,%3}, [%4];"
                 : "=r"(r[0]), "=r"(r[1]), "=r"(r[2]), "=r"(r[3]) : "r"(addr));
}
static __device__ __forceinline__ void cpasync16(unsigned dst, const void* src) {
    asm volatile("cp.async.cg.shared.global [%0], [%1], 16;" :: "r"(dst), "l"(src));
}
static __device__ __forceinline__ void mbar_init(unsigned mb, unsigned cnt) {
    asm volatile("mbarrier.init.shared.b64 [%0], %1;" :: "r"(mb), "r"(cnt) : "memory");
}
static __device__ __forceinline__ void mbar_arrive(unsigned mb) {
    asm volatile("mbarrier.arrive.shared.b64 _, [%0];" :: "r"(mb) : "memory");
}
// .noinc: this thread's arrival counts against the init count (64 producers).
static __device__ __forceinline__ void cpasync_mbar_arrive(unsigned mb) {
    asm volatile("cp.async.mbarrier.arrive.noinc.shared::cta.b64 [%0];"
                 :: "r"(mb) : "memory");
}
static __device__ __forceinline__ void mbar_wait(unsigned mb, unsigned parity) {
    asm volatile(
        "{\n\t.reg .pred P;\n\t"
        "WAIT_%=:\n\t"
        "mbarrier.try_wait.parity.acquire.cta.shared::cta.b64 P, [%0], %1, 0x989680;\n\t"
        "@P bra.uni DONE_%=;\n\t"
        "bra.uni WAIT_%=;\n\t"
        "DONE_%=:\n\t}"
        :: "r"(mb), "r"(parity) : "memory");
}

// ---------------------------------------------------------------------------
// Fused front-end: prep (blocks 0..1055) + weight synth (blocks 1056..1311).
// ---------------------------------------------------------------------------
#define PREP_BLOCKS (XP * B_)   // 1056

__global__ void __launch_bounds__(256) front_kernel(
    const float* __restrict__ x,
    const float* __restrict__ feature, const float* __restrict__ weight,
    const float* __restrict__ t0, const float* __restrict__ t1,
    const float* __restrict__ t2, const float* __restrict__ t3,
    const float* __restrict__ m0, const float* __restrict__ m1,
    const float* __restrict__ m2, const float* __restrict__ m3) {
    __shared__ __align__(16) __half sh[64 * 264];
    const int t = threadIdx.x;

    if (blockIdx.x < PREP_BLOCKS) {
        const int row = blockIdx.x % XP;
        const int b   = blockIdx.x / XP;
        __half* dst = g_xc + ((size_t)b * XP + row) * XP * CIN;

        if (row == 0 || row == XP - 1) {
            for (int i = t; i < XP * CIN / 8; i += 256)
                ((uint4*)dst)[i] = make_uint4(0, 0, 0, 0);
            return;
        }
        const int y = row - 1;
        const float* xr = x + (((size_t)b * CIN + t) * HW + y) * HW;
#pragma unroll
        for (int x4 = 0; x4 < 16; x4++) {
            float4 v = ((const float4*)xr)[x4];
            int xx = x4 * 4;
            sh[(xx + 0) * 264 + t] = __float2half(v.x);
            sh[(xx + 1) * 264 + t] = __float2half(v.y);
            sh[(xx + 2) * 264 + t] = __float2half(v.z);
            sh[(xx + 3) * 264 + t] = __float2half(v.w);
        }
        __syncthreads();
        {
            int col = 1 + (t >> 2);
            int ch  = (t & 3) * 64;
            uint4* d4 = (uint4*)(dst + (size_t)col * CIN + ch);
            const uint4* s4 = (const uint4*)(sh + (col - 1) * 264 + ch);
#pragma unroll
            for (int i = 0; i < 8; i++) d4[i] = s4[i];
        }
        if (t < 64) {
            int c = (t < 32) ? 0 : (XP - 1);
            ((uint4*)(dst + (size_t)c * CIN))[t & 31] = make_uint4(0, 0, 0, 0);
        }
    } else {
        __shared__ float sf[B_ * 4];
        if (t < B_ * 4) sf[t] = feature[t];
        __syncthreads();

        int idx = (blockIdx.x - PREP_BLOCKS) * 256 + t;
        int kx  = idx & 3;
        int ky  = (idx >> 2) & 3;
        int co  = (idx >> 4) & (COUT - 1);
        int ci0 = (idx >> 11) * 8;

        float w[8], a0[8], a1[8], a2[8], a3[8];
#pragma unroll
        for (int i = 0; i < 8; i++) {
            int ci  = ci0 + i;
            int off = (ci * COUT + co) * 16 + ky * 4 + kx;
            int mi  = ci * COUT + co;
            w[i]  = weight[off];
            a0[i] = t0[off] * m0[mi];
            a1[i] = t1[off] * m1[mi];
            a2[i] = t2[off] * m2[mi];
            a3[i] = t3[off] * m3[mi];
        }
        int py = 1 - (ky & 1);
        int px = 1 - (kx & 1);
        int dy = (py + 1 - ky) / 2;
        int dx = (px + 1 - kx) / 2;
        int ty = dy + 1 - py;
        int tx = dx + 1 - px;
        int p  = py * 2 + px;
        int q  = ty * 2 + tx;

        size_t base     = ((size_t)p * COUT + co) * KDIM + q * 256 + ci0;
        size_t stride_b = (size_t)4 * COUT * KDIM;
#pragma unroll
        for (int b = 0; b < B_; b++) {
            const float* f = sf + b * 4;
            __align__(16) __half h[8];
#pragma unroll
            for (int i = 0; i < 8; i++)
                h[i] = __float2half(w[i] + a0[i] * f[0] + a1[i] * f[1] +
                                    a2[i] * f[2] + a3[i] * f[3]);
            *(uint4*)(g_wsyn + b * stride_b + base) = *(uint4*)h;
        }
    }
}

// ---------------------------------------------------------------------------
// GEMM: warp-specialized. 8 consumer warps (2x4 grid, 64x64 warp tiles,
// mma.sync m16n8k16) + 2 producer warps (all cp.async fills).
// 4-slot mbarrier ring, no __syncthreads in the mainloop.
// CTA per (b, p, 256-spatial tile): M=128 x N=256 x K=1024.
// ---------------------------------------------------------------------------
#define MB_BASE (NSLOT * STG_BYTES)          // 196608
#define MB_FULL(s)  (MB_BASE + (s) * 16)
#define MB_EMPTY(s) (MB_BASE + (s) * 16 + 8)
#define SMEM_GEMM (MB_BASE + NSLOT * 16)

__global__ void __launch_bounds__(NTHREADS, 1)
deconv_mma_kernel(const float* __restrict__ bias,
                  const float* __restrict__ prelu_a,
                  float* __restrict__ out) {
    extern __shared__ __align__(1024) char smem[];
    const unsigned sb = (unsigned)__cvta_generic_to_shared(smem);
    const int tid  = threadIdx.x;
    const int lane = tid & 31;
    const int warp = tid >> 5;
    const int b  = blockIdx.z;
    const int p  = blockIdx.y;
    const int py = p >> 1, px = p & 1;
    const int n0 = blockIdx.x * NTILE;
    const int y0 = n0 >> 6;

    if (tid == 0) {
#pragma unroll
        for (int s = 0; s < NSLOT; s++) {
            mbar_init(sb + MB_FULL(s), 64);    // 64 producer threads cp-arrive
            mbar_init(sb + MB_EMPTY(s), 256);  // 256 consumer threads arrive
        }
    }
    __syncthreads();

    if (warp >= 8) {
        // ---------------- producer warps (2 warps, 64 threads) ----------------
        const int ptid = tid - 256;           // 0..63
        const __half* wb = g_wsyn + (size_t)(b * 4 + p) * COUT * KDIM;
        const __half* xb = g_xc + (size_t)b * XP * XP * CIN;

        for (int ks = 0; ks < NK; ks++) {
            const int slot = ks & 3;
            mbar_wait(sb + MB_EMPTY(slot), 1u ^ ((ks >> 2) & 1));
            const unsigned ab = sb + slot * STG_BYTES;
            const unsigned bb = ab + 16384;
            const int k0 = ks * KS;
            // A: 1024 x 16B segments
#pragma unroll
            for (int i = 0; i < 16; i++) {
                int seg = ptid + i * 64;
                int co = seg >> 3, s8 = seg & 7;
                cpasync16(ab + SWZ(co * 128 + s8 * 16),
                          wb + (size_t)co * KDIM + k0 + s8 * 8);
            }
            // B: 2048 x 16B segments
            const int q  = ks >> 2;
            const int ty = q >> 1, tx = q & 1;
            const int ci0 = (ks & 3) * 64;
#pragma unroll
            for (int i = 0; i < 32; i++) {
                int seg = ptid + i * 64;
                int n = seg >> 3, s8 = seg & 7;
                int yy  = y0 + (n >> 6) + ty + py;
                int xx2 = (n & 63) + tx + px;
                cpasync16(bb + SWZ(n * 128 + s8 * 16),
                          xb + ((size_t)yy * XP + xx2) * CIN + ci0 + s8 * 8);
            }
            cpasync_mbar_arrive(sb + MB_FULL(slot));
        }
        return;
    }

    // ---------------- consumer warps (8 warps) ----------------
    const int warp_m = warp >> 2;
    const int warp_n = warp & 3;

    // Fragment row bases + per-fragment swizzle masks (validated in R8):
    // SWZ(row*128 + kb) = row*128 + (kb ^ ((row&7)<<4)) for kb < 128.
    unsigned araw[4], amask[4], braw[4], bmask[4];
#pragma unroll
    for (int mi = 0; mi < 4; mi++) {
        int row = warp_m * 64 + mi * 16 + (lane & 15);
        araw[mi]  = row * 128;
        amask[mi] = (row & 7) << 4;
    }
#pragma unroll
    for (int g = 0; g < 4; g++) {
        int rown = warp_n * 64 + g * 16 + (lane & 15);
        braw[g]  = rown * 128;
        bmask[g] = (rown & 7) << 4;
    }
    const unsigned kbl = (lane >> 4) * 16;

    float acc[4][8][4];
#pragma unroll
    for (int i = 0; i < 4; i++)
#pragma unroll
        for (int j = 0; j < 8; j++)
#pragma unroll
            for (int r = 0; r < 4; r++) acc[i][j][r] = 0.f;

    for (int ks = 0; ks < NK; ks++) {
        const int slot = ks & 3;
        mbar_wait(sb + MB_FULL(slot), (ks >> 2) & 1);
        const unsigned ab = sb + slot * STG_BYTES;
        const unsigned bb = ab + 16384;
#pragma unroll
        for (int kk = 0; kk < 4; kk++) {
            const unsigned kkb = kbl + kk * 32;
            unsigned afr[4][4], bfr[4][4];
#pragma unroll
            for (int mi = 0; mi < 4; mi++)
                ldsm4(afr[mi], ab + araw[mi] + (kkb ^ amask[mi]));
#pragma unroll
            for (int g = 0; g < 4; g++)
                ldsm4(bfr[g], bb + braw[g] + (kkb ^ bmask[g]));
#pragma unroll
            for (int mi = 0; mi < 4; mi++)
#pragma unroll
                for (int nj = 0; nj < 8; nj++)
                    mma16816(acc[mi][nj], afr[mi][0], afr[mi][1], afr[mi][2],
                             afr[mi][3], bfr[nj >> 1][nj & 1],
                             bfr[nj >> 1][(nj & 1) + 2]);
        }
        mbar_arrive(sb + MB_EMPTY(slot));
    }

    // --- epilogue: bias + PReLU + stride-2 phase scatter ---
    const float alpha = prelu_a[0];
#pragma unroll
    for (int mi = 0; mi < 4; mi++) {
        const int rbase = warp_m * 64 + mi * 16 + (lane >> 2);
#pragma unroll
        for (int hm = 0; hm < 2; hm++) {
            const int co = rbase + hm * 8;
            const float bv = bias[co];
            float* obase = out + ((size_t)b * COUT + co) * OHW * OHW;
#pragma unroll
            for (int nj = 0; nj < 8; nj++) {
#pragma unroll
                for (int u = 0; u < 2; u++) {
                    int n  = n0 + warp_n * 64 + nj * 8 + (lane & 3) * 2 + u;
                    int y  = n >> 6;
                    int xx = n & 63;
                    int oy = 2 * y + py;
                    int ox = 2 * xx + px;
                    float v = acc[mi][nj][hm * 2 + u] + bv;
                    v = (v >= 0.f) ? v : alpha * v;
                    obase[oy * OHW + ox] = v;
                }
            }
        }
    }
}

// ---------------------------------------------------------------------------
// Launch
// ---------------------------------------------------------------------------
extern "C" void kernel_launch(void* const* d_in, const int* in_sizes, int n_in,
                              void* d_out, int out_size) {
    const float* x       = (const float*)d_in[0];
    const float* feature = (const float*)d_in[1];
    const float* weight  = (const float*)d_in[2];
    const float* t0      = (const float*)d_in[3];
    const float* t1      = (const float*)d_in[4];
    const float* t2      = (const float*)d_in[5];
    const float* t3      = (const float*)d_in[6];
    const float* m0      = (const float*)d_in[7];
    const float* m1      = (const float*)d_in[8];
    const float* m2      = (const float*)d_in[9];
    const float* m3      = (const float*)d_in[10];
    const float* bias    = (const float*)d_in[11];
    const float* prelu_a = (const float*)d_in[12];
    float* out = (float*)d_out;

    {
        int blocks = PREP_BLOCKS + (CIN / 8) * COUT * 16 / 256;  // 1056 + 256
        front_kernel<<<blocks, 256>>>(x, feature, weight, t0, t1, t2, t3,
                                      m0, m1, m2, m3);
    }
    {
        cudaFuncSetAttribute(deconv_mma_kernel,
                             cudaFuncAttributeMaxDynamicSharedMemorySize,
                             SMEM_GEMM);
        dim3 grid(HW * HW / NTILE, 4, B_);   // 16 x 4 x 16
        deconv_mma_kernel<<<grid, NTHREADS, SMEM_GEMM>>>(bias, prelu_a, out);
    }
}